// round 10
// baseline (speedup 1.0000x reference)
#include <cuda_runtime.h>

#define BATCH   32768
#define NCONT   56
#define NB      16
#define NCAT    8
#define NUNIQ   100
#define NCOMP   8
#define TPB     256
#define WARPS   8
#define RPW     8            // rows per warp
#define RPB     64           // rows per block
#define NCHUNK  14           // 56 features / 4 per chunk
#define FPITCH  20
#define RPITCH  80           // staged floats per row (4 * 20)
#define BUF_F   (RPW*RPITCH) // 640 floats per warp
#define SEPF    1e-3f
#define T1F     10.0f

// smem float offsets
#define SBUF    0
#define SWIC    (WARPS*BUF_F)            // 5120
#define SCODE   (SWIC + NB*NCONT)        // 6016 (ints)
#define SMEM_F  (SCODE + WARPS*RPW*NCAT) // 6528 floats = 26,112 B

// Stable softplus via fast intrinsics (err << 1e-3 budget; verified 5.8e-8 rel).
__device__ __forceinline__ float sp(float x) {
    float e = __expf(-fabsf(x));
    return fmaxf(x, 0.0f) + __logf(1.0f + e);
}

extern __shared__ float smem[];

__global__ void __launch_bounds__(TPB, 2) k_main(
    const float* __restrict__ B,
    const float* __restrict__ Bcat,
    const float* __restrict__ Wh,  const float* __restrict__ bh,
    const float* __restrict__ Wv,  const float* __restrict__ bv,
    const float* __restrict__ Wic, const float* __restrict__ bic,
    const float* __restrict__ Whc, const float* __restrict__ Wvc,
    const float* __restrict__ Wicc,
    float* __restrict__ out)
{
    const int tid  = threadIdx.x;
    const int wid  = tid >> 5;
    const int lane = tid & 31;
    const int rp   = lane >> 2;        // 0..7 row within warp
    const int fg   = lane & 3;         // 0..3 feature slot

    float* sBuf  = smem + SBUF + wid * BUF_F;
    float* sWic  = smem + SWIC;
    int*   scode = reinterpret_cast<int*>(smem + SCODE) + wid * (RPW * NCAT);

    const int row0 = blockIdx.x * RPB + wid * RPW;
    const int row  = row0 + rp;

    // ---- stage Wic (block-wide, coalesced; 896 floats) ----
    if (tid < 224)
        reinterpret_cast<float4*>(sWic)[tid] =
            __ldg(reinterpret_cast<const float4*>(Wic) + tid);

    // ---- warp-cooperative one-hot scan over 8 rows (coalesced) ----
    {
        const float4* gC = reinterpret_cast<const float4*>(Bcat);
        for (int rr = 0; rr < RPW; rr++) {
            const float4* base = gC + (size_t)(row0 + rr) * 200;
            #pragma unroll
            for (int t = 0; t < 7; t++) {
                int j = lane + t * 32;
                if (j < 200) {
                    float4 v = __ldg(base + j);
                    if (v.x > 0.5f || v.y > 0.5f || v.z > 0.5f || v.w > 0.5f) {
                        float vals[4] = {v.x, v.y, v.z, v.w};
                        #pragma unroll
                        for (int q = 0; q < 4; q++) {
                            if (vals[q] > 0.5f) {
                                int pos = j * 4 + q;
                                int f = pos / 100;
                                scode[rr * NCAT + f] = pos - f * 100;
                            }
                        }
                    }
                }
            }
        }
    }
    __syncthreads();   // Wic staged + codes visible

    float hs[NCOMP], vs[NCOMP];
    #pragma unroll
    for (int c = 0; c < NCOMP; c++) { hs[c] = 0.0f; vs[c] = 0.0f; }
    float ic = 0.0f;

    // ---- categorical gathers: this lane handles cat features fg and fg+4 ----
    #pragma unroll
    for (int cf = 0; cf < 2; cf++) {
        const int f = fg + cf * 4;
        const int code = scode[rp * NCAT + f];
        const int wrow = (f * NUNIQ + code) * NCOMP;
        float4 a0 = __ldg(reinterpret_cast<const float4*>(Whc + wrow));
        float4 a1 = __ldg(reinterpret_cast<const float4*>(Whc + wrow) + 1);
        float4 b0 = __ldg(reinterpret_cast<const float4*>(Wvc + wrow));
        float4 b1 = __ldg(reinterpret_cast<const float4*>(Wvc + wrow) + 1);
        hs[0]+=sp(a0.x); hs[1]+=sp(a0.y); hs[2]+=sp(a0.z); hs[3]+=sp(a0.w);
        hs[4]+=sp(a1.x); hs[5]+=sp(a1.y); hs[6]+=sp(a1.z); hs[7]+=sp(a1.w);
        vs[0]+=sp(b0.x); vs[1]+=sp(b0.y); vs[2]+=sp(b0.z); vs[3]+=sp(b0.w);
        vs[4]+=sp(b1.x); vs[5]+=sp(b1.y); vs[6]+=sp(b1.z); vs[7]+=sp(b1.w);
        ic += __ldg(Wicc + f * NUNIQ + code);
    }

    // ---- B staging geometry (R6 pipeline: proven conflict-light) ----
    const int rs_b = lane >> 4;          // 0/1 row parity
    const int m    = lane & 15;          // f4 index within 2-row slice
    const float4* ldg0 = reinterpret_cast<const float4*>(B) + (size_t)(row0 + 0 + rs_b) * 224 + m;
    const float4* ldg1 = reinterpret_cast<const float4*>(B) + (size_t)(row0 + 2 + rs_b) * 224 + m;
    const float4* ldg2 = reinterpret_cast<const float4*>(B) + (size_t)(row0 + 4 + rs_b) * 224 + m;
    const float4* ldg3 = reinterpret_cast<const float4*>(B) + (size_t)(row0 + 6 + rs_b) * 224 + m;
    float* sts0 = sBuf + (0 + rs_b) * RPITCH + (m >> 2) * FPITCH + (m & 3) * 4;
    float* sts1 = sts0 + 2 * RPITCH;
    float* sts2 = sts0 + 4 * RPITCH;
    float* sts3 = sts0 + 6 * RPITCH;

    float4 nb0 = __ldg(ldg0), nb1 = __ldg(ldg1), nb2 = __ldg(ldg2), nb3 = __ldg(ldg3);
    ldg0 += 16; ldg1 += 16; ldg2 += 16; ldg3 += 16;

    const float* bbase = sBuf + rp * RPITCH + fg * FPITCH;

    for (int ch = 0; ch < NCHUNK; ch++) {
        __syncwarp();
        *reinterpret_cast<float4*>(sts0) = nb0;
        *reinterpret_cast<float4*>(sts1) = nb1;
        *reinterpret_cast<float4*>(sts2) = nb2;
        *reinterpret_cast<float4*>(sts3) = nb3;
        __syncwarp();
        if (ch + 1 < NCHUNK) {
            nb0 = __ldg(ldg0); nb1 = __ldg(ldg1);
            nb2 = __ldg(ldg2); nb3 = __ldg(ldg3);
            ldg0 += 16; ldg1 += 16; ldg2 += 16; ldg3 += 16;
        }

        const int f = ch * 4 + fg;

        // ---------- H subloop (+ IC) ----------
        {
            float h[NCOMP];
            #pragma unroll
            for (int c = 0; c < NCOMP; c++) h[c] = 0.0f;
            const float4* wp = reinterpret_cast<const float4*>(Wh) + f * 2;
            const float* wicp = sWic + f;
            #pragma unroll
            for (int k4 = 0; k4 < 4; k4++) {
                float4 b4 = *reinterpret_cast<const float4*>(bbase + k4 * 4);
                float bk[4] = {b4.x, b4.y, b4.z, b4.w};
                #pragma unroll
                for (int kk = 0; kk < 4; kk++) {
                    const int k = k4 * 4 + kk;
                    float4 w0 = __ldg(wp + k * 112);
                    float4 w1 = __ldg(wp + k * 112 + 1);
                    float wic = wicp[k * NCONT];
                    const float a = bk[kk];
                    h[0]=fmaf(a,w0.x,h[0]); h[1]=fmaf(a,w0.y,h[1]);
                    h[2]=fmaf(a,w0.z,h[2]); h[3]=fmaf(a,w0.w,h[3]);
                    h[4]=fmaf(a,w1.x,h[4]); h[5]=fmaf(a,w1.y,h[5]);
                    h[6]=fmaf(a,w1.z,h[6]); h[7]=fmaf(a,w1.w,h[7]);
                    ic  = fmaf(a, wic, ic);
                }
            }
            #pragma unroll
            for (int c = 0; c < NCOMP; c++) hs[c] += sp(h[c]);
        }

        // ---------- V subloop ----------
        {
            float v[NCOMP];
            #pragma unroll
            for (int c = 0; c < NCOMP; c++) v[c] = 0.0f;
            const float4* wp = reinterpret_cast<const float4*>(Wv) + f * 2;
            #pragma unroll
            for (int k4 = 0; k4 < 4; k4++) {
                float4 b4 = *reinterpret_cast<const float4*>(bbase + k4 * 4);
                float bk[4] = {b4.x, b4.y, b4.z, b4.w};
                #pragma unroll
                for (int kk = 0; kk < 4; kk++) {
                    const int k = k4 * 4 + kk;
                    float4 w0 = __ldg(wp + k * 112);
                    float4 w1 = __ldg(wp + k * 112 + 1);
                    const float a = bk[kk];
                    v[0]=fmaf(a,w0.x,v[0]); v[1]=fmaf(a,w0.y,v[1]);
                    v[2]=fmaf(a,w0.z,v[2]); v[3]=fmaf(a,w0.w,v[3]);
                    v[4]=fmaf(a,w1.x,v[4]); v[5]=fmaf(a,w1.y,v[5]);
                    v[6]=fmaf(a,w1.z,v[6]); v[7]=fmaf(a,w1.w,v[7]);
                }
            }
            #pragma unroll
            for (int c = 0; c < NCOMP; c++) vs[c] += sp(v[c]);
        }
    }

    // ---- reduce over the 4 fg lanes ----
    #pragma unroll
    for (int c = 0; c < NCOMP; c++) {
        hs[c] += __shfl_xor_sync(0xffffffffu, hs[c], 1);
        hs[c] += __shfl_xor_sync(0xffffffffu, hs[c], 2);
        vs[c] += __shfl_xor_sync(0xffffffffu, vs[c], 1);
        vs[c] += __shfl_xor_sync(0xffffffffu, vs[c], 2);
    }
    ic += __shfl_xor_sync(0xffffffffu, ic, 1);
    ic += __shfl_xor_sync(0xffffffffu, ic, 2);

    if (fg == 0) {
        #pragma unroll
        for (int c = 0; c < NCOMP; c++) {
            hs[c] += sp(__ldg(bh + c));
            vs[c] += sp(__ldg(bv + c));
        }
        ic += __ldg(bic);

        float2 o[NCOMP + 1];
        o[0] = make_float2(0.0f, ic);
        float cum = 0.0f, xc = ic;
        #pragma unroll
        for (int c = 0; c < NCOMP; c++) {
            cum += hs[c];
            xc  += (c & 1) ? -vs[c] : vs[c];
            o[c + 1] = make_float2(cum + SEPF * (float)(c + 1), xc);
        }
        o[NCOMP].x = fmaxf(o[NCOMP - 1].x + SEPF, T1F);

        float2* op = reinterpret_cast<float2*>(out + (size_t)row * 2 * (NCOMP + 1));
        #pragma unroll
        for (int j = 0; j < NCOMP + 1; j++) op[j] = o[j];
    }
}

extern "C" void kernel_launch(void* const* d_in, const int* in_sizes, int n_in,
                              void* d_out, int out_size)
{
    const float* B    = (const float*)d_in[0];
    const float* Bcat = (const float*)d_in[1];
    const float* Wh   = (const float*)d_in[2];
    const float* Whc  = (const float*)d_in[3];
    const float* bh   = (const float*)d_in[4];
    const float* Wv   = (const float*)d_in[5];
    const float* Wvc  = (const float*)d_in[6];
    const float* bv   = (const float*)d_in[7];
    const float* Wic  = (const float*)d_in[8];
    const float* Wicc = (const float*)d_in[9];
    const float* bic  = (const float*)d_in[10];
    float* out = (float*)d_out;

    const size_t smem = SMEM_F * sizeof(float);   // 26,112 B
    k_main<<<BATCH / RPB, TPB, smem>>>(B, Bcat, Wh, bh, Wv, bv, Wic, bic,
                                       Whc, Wvc, Wicc, out);
}

// round 12
// speedup vs baseline: 1.7473x; 1.7473x over previous
#include <cuda_runtime.h>
#include <cstdint>

#define BATCH   32768
#define NCONT   56
#define NB      16
#define NCAT    8
#define NUNIQ   100
#define NCOMP   8
#define TPB     128
#define WARPS   4
#define RPW     16           // rows per warp (dual-row: rp and rp+8)
#define RPB     64           // rows per block
#define NCHUNK  14           // 56 features / 4
#define FPITCH  20
#define RPITCH  80           // floats per staged row (4 features * 20)
#define CBUF_F  (RPW*RPITCH) // 1280 floats per chunk buffer
#define BUF_F   (2*CBUF_F)   // double-buffered per warp
#define SEPF    1e-3f
#define T1F     10.0f

// smem float offsets
#define SBUF    0
#define SWIC    (WARPS*BUF_F)                 // 10240
#define SCODE   (SWIC + NB*NCONT)             // 11136 (ints)
#define SMEM_F  (SCODE + WARPS*RPW*NCAT)      // 11648 floats = 46,592 B (<48KB)

__device__ __forceinline__ void cp16(float* dst_smem, const float4* src) {
    uint32_t d = (uint32_t)__cvta_generic_to_shared(dst_smem);
    asm volatile("cp.async.ca.shared.global [%0], [%1], 16;\n" :: "r"(d), "l"(src));
}
#define CP_COMMIT()  asm volatile("cp.async.commit_group;\n")
#define CP_WAIT1()   asm volatile("cp.async.wait_group 1;\n")
#define CP_WAIT0()   asm volatile("cp.async.wait_group 0;\n")

// Stable softplus via fast intrinsics (err << 1e-3 budget; verified 5.8e-8 rel).
__device__ __forceinline__ float sp(float x) {
    float e = __expf(-fabsf(x));
    return fmaxf(x, 0.0f) + __logf(1.0f + e);
}

extern __shared__ float smem[];

__global__ void __launch_bounds__(TPB, 4) k_main(
    const float* __restrict__ B,
    const float* __restrict__ Bcat,
    const float* __restrict__ Wh,  const float* __restrict__ bh,
    const float* __restrict__ Wv,  const float* __restrict__ bv,
    const float* __restrict__ Wic, const float* __restrict__ bic,
    const float* __restrict__ Whc, const float* __restrict__ Wvc,
    const float* __restrict__ Wicc,
    float* __restrict__ out)
{
    const int tid  = threadIdx.x;
    const int wid  = tid >> 5;
    const int lane = tid & 31;
    const int rp   = lane >> 2;        // 0..7 row-pair id
    const int fg   = lane & 3;         // 0..3 feature slot

    float* sBuf  = smem + SBUF + wid * BUF_F;
    float* sWic  = smem + SWIC;
    int*   scode = reinterpret_cast<int*>(smem + SCODE) + wid * (RPW * NCAT);

    const int row0 = blockIdx.x * RPB + wid * RPW;

    // ---- stage Wic (block-wide, coalesced; 224 float4) ----
    for (int i = tid; i < 224; i += TPB)
        reinterpret_cast<float4*>(sWic)[i] =
            __ldg(reinterpret_cast<const float4*>(Wic) + i);

    // ---- warp-cooperative one-hot scan over 16 rows (coalesced) ----
    {
        const float4* gC = reinterpret_cast<const float4*>(Bcat);
        for (int rr = 0; rr < RPW; rr++) {
            const float4* base = gC + (size_t)(row0 + rr) * 200;
            #pragma unroll
            for (int t = 0; t < 7; t++) {
                int j = lane + t * 32;
                if (j < 200) {
                    float4 v = __ldg(base + j);
                    if (v.x > 0.5f || v.y > 0.5f || v.z > 0.5f || v.w > 0.5f) {
                        float vals[4] = {v.x, v.y, v.z, v.w};
                        #pragma unroll
                        for (int q = 0; q < 4; q++) {
                            if (vals[q] > 0.5f) {
                                int pos = j * 4 + q;
                                int f = pos / 100;
                                scode[rr * NCAT + f] = pos - f * 100;
                            }
                        }
                    }
                }
            }
        }
    }
    __syncthreads();   // Wic staged + codes visible

    float hsA[NCOMP], vsA[NCOMP], hsB[NCOMP], vsB[NCOMP];
    #pragma unroll
    for (int c = 0; c < NCOMP; c++) { hsA[c]=0.f; vsA[c]=0.f; hsB[c]=0.f; vsB[c]=0.f; }
    float icA = 0.f, icB = 0.f;

    // ---- categorical gathers: features {fg, fg+4} x rows {rp, rp+8} ----
    #pragma unroll
    for (int cf = 0; cf < 2; cf++) {
        const int f = fg + cf * 4;
        {
            const int code = scode[rp * NCAT + f];
            const int wrow = (f * NUNIQ + code) * NCOMP;
            float4 a0 = __ldg(reinterpret_cast<const float4*>(Whc + wrow));
            float4 a1 = __ldg(reinterpret_cast<const float4*>(Whc + wrow) + 1);
            float4 b0 = __ldg(reinterpret_cast<const float4*>(Wvc + wrow));
            float4 b1 = __ldg(reinterpret_cast<const float4*>(Wvc + wrow) + 1);
            hsA[0]+=sp(a0.x); hsA[1]+=sp(a0.y); hsA[2]+=sp(a0.z); hsA[3]+=sp(a0.w);
            hsA[4]+=sp(a1.x); hsA[5]+=sp(a1.y); hsA[6]+=sp(a1.z); hsA[7]+=sp(a1.w);
            vsA[0]+=sp(b0.x); vsA[1]+=sp(b0.y); vsA[2]+=sp(b0.z); vsA[3]+=sp(b0.w);
            vsA[4]+=sp(b1.x); vsA[5]+=sp(b1.y); vsA[6]+=sp(b1.z); vsA[7]+=sp(b1.w);
            icA += __ldg(Wicc + f * NUNIQ + code);
        }
        {
            const int code = scode[(rp + 8) * NCAT + f];
            const int wrow = (f * NUNIQ + code) * NCOMP;
            float4 a0 = __ldg(reinterpret_cast<const float4*>(Whc + wrow));
            float4 a1 = __ldg(reinterpret_cast<const float4*>(Whc + wrow) + 1);
            float4 b0 = __ldg(reinterpret_cast<const float4*>(Wvc + wrow));
            float4 b1 = __ldg(reinterpret_cast<const float4*>(Wvc + wrow) + 1);
            hsB[0]+=sp(a0.x); hsB[1]+=sp(a0.y); hsB[2]+=sp(a0.z); hsB[3]+=sp(a0.w);
            hsB[4]+=sp(a1.x); hsB[5]+=sp(a1.y); hsB[6]+=sp(a1.z); hsB[7]+=sp(a1.w);
            vsB[0]+=sp(b0.x); vsB[1]+=sp(b0.y); vsB[2]+=sp(b0.z); vsB[3]+=sp(b0.w);
            vsB[4]+=sp(b1.x); vsB[5]+=sp(b1.y); vsB[6]+=sp(b1.z); vsB[7]+=sp(b1.w);
            icB += __ldg(Wicc + f * NUNIQ + code);
        }
    }

    // ---- cp.async staging geometry: lane copies (rows 2t+srow, f4 m) ----
    const int srow = lane >> 4;          // 0/1
    const int m    = lane & 15;          // f4 index within a row's chunk slice
    const float4* gsrc = reinterpret_cast<const float4*>(B) + (size_t)(row0 + srow) * 224 + m;
    const int dstoff = srow * RPITCH + (m >> 2) * FPITCH + (m & 3) * 4;

    // prologue: stage chunk 0 into buffer 0
    {
        const float4* s = gsrc;
        float* d = sBuf + dstoff;
        #pragma unroll
        for (int t = 0; t < 8; t++) cp16(d + t * (2 * RPITCH), s + t * (2 * 224));
        CP_COMMIT();
    }

    const float* bAbase = sBuf + rp * RPITCH + fg * FPITCH;

    for (int ch = 0; ch < NCHUNK; ch++) {
        const int bi = ch & 1;
        if (ch + 1 < NCHUNK) {
            const float4* s = gsrc + (ch + 1) * 16;
            float* d = sBuf + (bi ^ 1) * CBUF_F + dstoff;
            #pragma unroll
            for (int t = 0; t < 8; t++) cp16(d + t * (2 * RPITCH), s + t * (2 * 224));
            CP_COMMIT();
            CP_WAIT1();
        } else {
            CP_WAIT0();
        }
        __syncwarp();

        const int f = ch * 4 + fg;
        const float* bA = bAbase + bi * CBUF_F;
        const float* bB = bA + 8 * RPITCH;

        // ---------- H pass (+ IC), dual-row ----------
        {
            float hA[NCOMP], hB[NCOMP];
            #pragma unroll
            for (int c = 0; c < NCOMP; c++) { hA[c] = 0.f; hB[c] = 0.f; }
            const float4* wp = reinterpret_cast<const float4*>(Wh) + f * 2;
            const float* wicp = sWic + f;
            #pragma unroll
            for (int k4 = 0; k4 < 4; k4++) {
                float4 a4 = *reinterpret_cast<const float4*>(bA + k4 * 4);
                float4 b4 = *reinterpret_cast<const float4*>(bB + k4 * 4);
                float ak[4] = {a4.x, a4.y, a4.z, a4.w};
                float bk[4] = {b4.x, b4.y, b4.z, b4.w};
                #pragma unroll
                for (int kk = 0; kk < 4; kk++) {
                    const int k = k4 * 4 + kk;
                    float4 w0 = __ldg(wp + k * 112);
                    float4 w1 = __ldg(wp + k * 112 + 1);
                    float wic = wicp[k * NCONT];
                    const float a = ak[kk], b = bk[kk];
                    hA[0]=fmaf(a,w0.x,hA[0]); hA[1]=fmaf(a,w0.y,hA[1]);
                    hA[2]=fmaf(a,w0.z,hA[2]); hA[3]=fmaf(a,w0.w,hA[3]);
                    hA[4]=fmaf(a,w1.x,hA[4]); hA[5]=fmaf(a,w1.y,hA[5]);
                    hA[6]=fmaf(a,w1.z,hA[6]); hA[7]=fmaf(a,w1.w,hA[7]);
                    hB[0]=fmaf(b,w0.x,hB[0]); hB[1]=fmaf(b,w0.y,hB[1]);
                    hB[2]=fmaf(b,w0.z,hB[2]); hB[3]=fmaf(b,w0.w,hB[3]);
                    hB[4]=fmaf(b,w1.x,hB[4]); hB[5]=fmaf(b,w1.y,hB[5]);
                    hB[6]=fmaf(b,w1.z,hB[6]); hB[7]=fmaf(b,w1.w,hB[7]);
                    icA = fmaf(a, wic, icA);
                    icB = fmaf(b, wic, icB);
                }
            }
            #pragma unroll
            for (int c = 0; c < NCOMP; c++) { hsA[c] += sp(hA[c]); hsB[c] += sp(hB[c]); }
        }

        // ---------- V pass, dual-row ----------
        {
            float vA[NCOMP], vB[NCOMP];
            #pragma unroll
            for (int c = 0; c < NCOMP; c++) { vA[c] = 0.f; vB[c] = 0.f; }
            const float4* wp = reinterpret_cast<const float4*>(Wv) + f * 2;
            #pragma unroll
            for (int k4 = 0; k4 < 4; k4++) {
                float4 a4 = *reinterpret_cast<const float4*>(bA + k4 * 4);
                float4 b4 = *reinterpret_cast<const float4*>(bB + k4 * 4);
                float ak[4] = {a4.x, a4.y, a4.z, a4.w};
                float bk[4] = {b4.x, b4.y, b4.z, b4.w};
                #pragma unroll
                for (int kk = 0; kk < 4; kk++) {
                    const int k = k4 * 4 + kk;
                    float4 w0 = __ldg(wp + k * 112);
                    float4 w1 = __ldg(wp + k * 112 + 1);
                    const float a = ak[kk], b = bk[kk];
                    vA[0]=fmaf(a,w0.x,vA[0]); vA[1]=fmaf(a,w0.y,vA[1]);
                    vA[2]=fmaf(a,w0.z,vA[2]); vA[3]=fmaf(a,w0.w,vA[3]);
                    vA[4]=fmaf(a,w1.x,vA[4]); vA[5]=fmaf(a,w1.y,vA[5]);
                    vA[6]=fmaf(a,w1.z,vA[6]); vA[7]=fmaf(a,w1.w,vA[7]);
                    vB[0]=fmaf(b,w0.x,vB[0]); vB[1]=fmaf(b,w0.y,vB[1]);
                    vB[2]=fmaf(b,w0.z,vB[2]); vB[3]=fmaf(b,w0.w,vB[3]);
                    vB[4]=fmaf(b,w1.x,vB[4]); vB[5]=fmaf(b,w1.y,vB[5]);
                    vB[6]=fmaf(b,w1.z,vB[6]); vB[7]=fmaf(b,w1.w,vB[7]);
                }
            }
            #pragma unroll
            for (int c = 0; c < NCOMP; c++) { vsA[c] += sp(vA[c]); vsB[c] += sp(vB[c]); }
        }

        __syncwarp();   // all lanes done reading buf bi before next-iter cp.async reuses it
    }

    // ---- reduce over the 4 fg lanes ----
    #pragma unroll
    for (int c = 0; c < NCOMP; c++) {
        hsA[c] += __shfl_xor_sync(0xffffffffu, hsA[c], 1);
        hsA[c] += __shfl_xor_sync(0xffffffffu, hsA[c], 2);
        vsA[c] += __shfl_xor_sync(0xffffffffu, vsA[c], 1);
        vsA[c] += __shfl_xor_sync(0xffffffffu, vsA[c], 2);
        hsB[c] += __shfl_xor_sync(0xffffffffu, hsB[c], 1);
        hsB[c] += __shfl_xor_sync(0xffffffffu, hsB[c], 2);
        vsB[c] += __shfl_xor_sync(0xffffffffu, vsB[c], 1);
        vsB[c] += __shfl_xor_sync(0xffffffffu, vsB[c], 2);
    }
    icA += __shfl_xor_sync(0xffffffffu, icA, 1);
    icA += __shfl_xor_sync(0xffffffffu, icA, 2);
    icB += __shfl_xor_sync(0xffffffffu, icB, 1);
    icB += __shfl_xor_sync(0xffffffffu, icB, 2);

    if (fg == 0) {
        #pragma unroll
        for (int c = 0; c < NCOMP; c++) {
            float sbh = sp(__ldg(bh + c));
            float sbv = sp(__ldg(bv + c));
            hsA[c] += sbh; hsB[c] += sbh;
            vsA[c] += sbv; vsB[c] += sbv;
        }
        float b0 = __ldg(bic);
        icA += b0; icB += b0;

        // row A = row0 + rp
        {
            float2 o[NCOMP + 1];
            o[0] = make_float2(0.0f, icA);
            float cum = 0.0f, xc = icA;
            #pragma unroll
            for (int c = 0; c < NCOMP; c++) {
                cum += hsA[c];
                xc  += (c & 1) ? -vsA[c] : vsA[c];
                o[c + 1] = make_float2(cum + SEPF * (float)(c + 1), xc);
            }
            o[NCOMP].x = fmaxf(o[NCOMP - 1].x + SEPF, T1F);
            float2* op = reinterpret_cast<float2*>(out + (size_t)(row0 + rp) * 2 * (NCOMP + 1));
            #pragma unroll
            for (int j = 0; j < NCOMP + 1; j++) op[j] = o[j];
        }
        // row B = row0 + rp + 8
        {
            float2 o[NCOMP + 1];
            o[0] = make_float2(0.0f, icB);
            float cum = 0.0f, xc = icB;
            #pragma unroll
            for (int c = 0; c < NCOMP; c++) {
                cum += hsB[c];
                xc  += (c & 1) ? -vsB[c] : vsB[c];
                o[c + 1] = make_float2(cum + SEPF * (float)(c + 1), xc);
            }
            o[NCOMP].x = fmaxf(o[NCOMP - 1].x + SEPF, T1F);
            float2* op = reinterpret_cast<float2*>(out + (size_t)(row0 + rp + 8) * 2 * (NCOMP + 1));
            #pragma unroll
            for (int j = 0; j < NCOMP + 1; j++) op[j] = o[j];
        }
    }
}

extern "C" void kernel_launch(void* const* d_in, const int* in_sizes, int n_in,
                              void* d_out, int out_size)
{
    const float* B    = (const float*)d_in[0];
    const float* Bcat = (const float*)d_in[1];
    const float* Wh   = (const float*)d_in[2];
    const float* Whc  = (const float*)d_in[3];
    const float* bh   = (const float*)d_in[4];
    const float* Wv   = (const float*)d_in[5];
    const float* Wvc  = (const float*)d_in[6];
    const float* bv   = (const float*)d_in[7];
    const float* Wic  = (const float*)d_in[8];
    const float* Wicc = (const float*)d_in[9];
    const float* bic  = (const float*)d_in[10];
    float* out = (float*)d_out;

    const size_t smem = SMEM_F * sizeof(float);   // 46,592 B (< 48 KB)
    k_main<<<BATCH / RPB, TPB, smem>>>(B, Bcat, Wh, bh, Wv, bv, Wic, bic,
                                       Whc, Wvc, Wicc, out);
}

// round 13
// speedup vs baseline: 2.0120x; 1.1515x over previous
#include <cuda_runtime.h>
#include <cstdint>

#define BATCH   32768
#define NCONT   56
#define NB      16
#define NCAT    8
#define NUNIQ   100
#define NCOMP   8
#define TPB     128
#define WARPS   4
#define RPW     16           // rows per warp (dual-row: rp and rp+8)
#define RPB     64           // rows per block
#define NCHUNK  14           // 56 features / 4
#define FPITCH  20
#define RPITCH  80           // floats per staged row (4 features * 20)
#define CBUF_F  (RPW*RPITCH) // 1280 floats per chunk buffer
#define BUF_F   (2*CBUF_F)   // double-buffered per warp
#define SEPF    1e-3f
#define T1F     10.0f

// smem float offsets (all warp-private: no __syncthreads needed anywhere)
#define SBUF    0
#define SCODE   (WARPS*BUF_F)                 // 10240 (ints)
#define SMEM_F  (SCODE + WARPS*RPW*NCAT)      // 10752 floats = 43,008 B

__device__ __forceinline__ void cp16(float* dst_smem, const float4* src) {
    uint32_t d = (uint32_t)__cvta_generic_to_shared(dst_smem);
    asm volatile("cp.async.ca.shared.global [%0], [%1], 16;\n" :: "r"(d), "l"(src));
}
#define CP_COMMIT()  asm volatile("cp.async.commit_group;\n")
#define CP_WAIT1()   asm volatile("cp.async.wait_group 1;\n")
#define CP_WAIT0()   asm volatile("cp.async.wait_group 0;\n")

// ---- f32x2 dual-FMA helpers (sm_103a) ----
__device__ __forceinline__ unsigned long long pack2(float a, float b) {
    unsigned long long r;
    asm("mov.b64 %0, {%1, %2};" : "=l"(r) : "f"(a), "f"(b));
    return r;
}
__device__ __forceinline__ void fma2(unsigned long long& d,
                                     unsigned long long a, unsigned long long b) {
    asm("fma.rn.f32x2 %0, %1, %2, %0;" : "+l"(d) : "l"(a), "l"(b));
}
__device__ __forceinline__ void unpack2(unsigned long long v, float& lo, float& hi) {
    asm("mov.b64 {%0, %1}, %2;" : "=f"(lo), "=f"(hi) : "l"(v));
}

// Stable softplus via fast intrinsics (err << 1e-3 budget; verified 5.8e-8 rel).
__device__ __forceinline__ float sp(float x) {
    float e = __expf(-fabsf(x));
    return fmaxf(x, 0.0f) + __logf(1.0f + e);
}

extern __shared__ float smem[];

__global__ void __launch_bounds__(TPB, 4) k_main(
    const float* __restrict__ B,
    const float* __restrict__ Bcat,
    const float* __restrict__ Wh,  const float* __restrict__ bh,
    const float* __restrict__ Wv,  const float* __restrict__ bv,
    const float* __restrict__ Wic, const float* __restrict__ bic,
    const float* __restrict__ Whc, const float* __restrict__ Wvc,
    const float* __restrict__ Wicc,
    float* __restrict__ out)
{
    const int tid  = threadIdx.x;
    const int wid  = tid >> 5;
    const int lane = tid & 31;
    const int rp   = lane >> 2;        // 0..7 row-pair id
    const int fg   = lane & 3;         // 0..3 feature slot

    float* sBuf  = smem + SBUF + wid * BUF_F;
    int*   scode = reinterpret_cast<int*>(smem + SCODE) + wid * (RPW * NCAT);

    const int row0 = blockIdx.x * RPB + wid * RPW;

    // ---- warp-cooperative one-hot scan over 16 rows (coalesced) ----
    {
        const float4* gC = reinterpret_cast<const float4*>(Bcat);
        for (int rr = 0; rr < RPW; rr++) {
            const float4* base = gC + (size_t)(row0 + rr) * 200;
            #pragma unroll
            for (int t = 0; t < 7; t++) {
                int j = lane + t * 32;
                if (j < 200) {
                    float4 v = __ldg(base + j);
                    if (v.x > 0.5f || v.y > 0.5f || v.z > 0.5f || v.w > 0.5f) {
                        float vals[4] = {v.x, v.y, v.z, v.w};
                        #pragma unroll
                        for (int q = 0; q < 4; q++) {
                            if (vals[q] > 0.5f) {
                                int pos = j * 4 + q;
                                int f = pos / 100;
                                scode[rr * NCAT + f] = pos - f * 100;
                            }
                        }
                    }
                }
            }
        }
    }
    __syncwarp();   // codes are warp-private: warp-level ordering suffices

    float hsA[NCOMP], vsA[NCOMP], hsB[NCOMP], vsB[NCOMP];
    #pragma unroll
    for (int c = 0; c < NCOMP; c++) { hsA[c]=0.f; vsA[c]=0.f; hsB[c]=0.f; vsB[c]=0.f; }
    float icA = 0.f, icB = 0.f;

    // ---- categorical gathers: features {fg, fg+4} x rows {rp, rp+8} ----
    #pragma unroll
    for (int cf = 0; cf < 2; cf++) {
        const int f = fg + cf * 4;
        {
            const int code = scode[rp * NCAT + f];
            const int wrow = (f * NUNIQ + code) * NCOMP;
            float4 a0 = __ldg(reinterpret_cast<const float4*>(Whc + wrow));
            float4 a1 = __ldg(reinterpret_cast<const float4*>(Whc + wrow) + 1);
            float4 b0 = __ldg(reinterpret_cast<const float4*>(Wvc + wrow));
            float4 b1 = __ldg(reinterpret_cast<const float4*>(Wvc + wrow) + 1);
            hsA[0]+=sp(a0.x); hsA[1]+=sp(a0.y); hsA[2]+=sp(a0.z); hsA[3]+=sp(a0.w);
            hsA[4]+=sp(a1.x); hsA[5]+=sp(a1.y); hsA[6]+=sp(a1.z); hsA[7]+=sp(a1.w);
            vsA[0]+=sp(b0.x); vsA[1]+=sp(b0.y); vsA[2]+=sp(b0.z); vsA[3]+=sp(b0.w);
            vsA[4]+=sp(b1.x); vsA[5]+=sp(b1.y); vsA[6]+=sp(b1.z); vsA[7]+=sp(b1.w);
            icA += __ldg(Wicc + f * NUNIQ + code);
        }
        {
            const int code = scode[(rp + 8) * NCAT + f];
            const int wrow = (f * NUNIQ + code) * NCOMP;
            float4 a0 = __ldg(reinterpret_cast<const float4*>(Whc + wrow));
            float4 a1 = __ldg(reinterpret_cast<const float4*>(Whc + wrow) + 1);
            float4 b0 = __ldg(reinterpret_cast<const float4*>(Wvc + wrow));
            float4 b1 = __ldg(reinterpret_cast<const float4*>(Wvc + wrow) + 1);
            hsB[0]+=sp(a0.x); hsB[1]+=sp(a0.y); hsB[2]+=sp(a0.z); hsB[3]+=sp(a0.w);
            hsB[4]+=sp(a1.x); hsB[5]+=sp(a1.y); hsB[6]+=sp(a1.z); hsB[7]+=sp(a1.w);
            vsB[0]+=sp(b0.x); vsB[1]+=sp(b0.y); vsB[2]+=sp(b0.z); vsB[3]+=sp(b0.w);
            vsB[4]+=sp(b1.x); vsB[5]+=sp(b1.y); vsB[6]+=sp(b1.z); vsB[7]+=sp(b1.w);
            icB += __ldg(Wicc + f * NUNIQ + code);
        }
    }

    // ---- cp.async staging geometry: lane copies (rows 2t+srow, f4 m) ----
    const int srow = lane >> 4;          // 0/1
    const int m    = lane & 15;          // f4 index within a row's chunk slice
    const float4* gsrc = reinterpret_cast<const float4*>(B) + (size_t)(row0 + srow) * 224 + m;
    const int dstoff = srow * RPITCH + (m >> 2) * FPITCH + (m & 3) * 4;

    // prologue: stage chunk 0 into buffer 0
    {
        const float4* s = gsrc;
        float* d = sBuf + dstoff;
        #pragma unroll
        for (int t = 0; t < 8; t++) cp16(d + t * (2 * RPITCH), s + t * (2 * 224));
        CP_COMMIT();
    }

    const float* bAbase = sBuf + rp * RPITCH + fg * FPITCH;

    for (int ch = 0; ch < NCHUNK; ch++) {
        const int bi = ch & 1;
        if (ch + 1 < NCHUNK) {
            const float4* s = gsrc + (ch + 1) * 16;
            float* d = sBuf + (bi ^ 1) * CBUF_F + dstoff;
            #pragma unroll
            for (int t = 0; t < 8; t++) cp16(d + t * (2 * RPITCH), s + t * (2 * 224));
            CP_COMMIT();
            CP_WAIT1();
        } else {
            CP_WAIT0();
        }
        __syncwarp();

        const int f = ch * 4 + fg;
        const float* bA = bAbase + bi * CBUF_F;
        const float* bB = bA + 8 * RPITCH;

        // ---------- H pass (+ IC), dual-row, f32x2 ----------
        {
            unsigned long long hA[4], hB[4];
            #pragma unroll
            for (int j = 0; j < 4; j++) { hA[j] = 0ull; hB[j] = 0ull; }
            const ulonglong2* wp = reinterpret_cast<const ulonglong2*>(Wh) + f * 2;
            const float* wicp = Wic + f;
            #pragma unroll
            for (int k4 = 0; k4 < 4; k4++) {
                float4 a4 = *reinterpret_cast<const float4*>(bA + k4 * 4);
                float4 b4 = *reinterpret_cast<const float4*>(bB + k4 * 4);
                float ak[4] = {a4.x, a4.y, a4.z, a4.w};
                float bk[4] = {b4.x, b4.y, b4.z, b4.w};
                #pragma unroll
                for (int kk = 0; kk < 4; kk++) {
                    const int k = k4 * 4 + kk;
                    ulonglong2 w01 = __ldg(wp + k * 112);
                    ulonglong2 w23 = __ldg(wp + k * 112 + 1);
                    float wic = __ldg(wicp + k * NCONT);
                    const float a = ak[kk], b = bk[kk];
                    unsigned long long aa = pack2(a, a);
                    unsigned long long bb = pack2(b, b);
                    fma2(hA[0], aa, w01.x); fma2(hA[1], aa, w01.y);
                    fma2(hA[2], aa, w23.x); fma2(hA[3], aa, w23.y);
                    fma2(hB[0], bb, w01.x); fma2(hB[1], bb, w01.y);
                    fma2(hB[2], bb, w23.x); fma2(hB[3], bb, w23.y);
                    icA = fmaf(a, wic, icA);
                    icB = fmaf(b, wic, icB);
                }
            }
            #pragma unroll
            for (int j = 0; j < 4; j++) {
                float lo, hi;
                unpack2(hA[j], lo, hi);
                hsA[2*j] += sp(lo); hsA[2*j+1] += sp(hi);
                unpack2(hB[j], lo, hi);
                hsB[2*j] += sp(lo); hsB[2*j+1] += sp(hi);
            }
        }

        // ---------- V pass, dual-row, f32x2 ----------
        {
            unsigned long long vA[4], vB[4];
            #pragma unroll
            for (int j = 0; j < 4; j++) { vA[j] = 0ull; vB[j] = 0ull; }
            const ulonglong2* wp = reinterpret_cast<const ulonglong2*>(Wv) + f * 2;
            #pragma unroll
            for (int k4 = 0; k4 < 4; k4++) {
                float4 a4 = *reinterpret_cast<const float4*>(bA + k4 * 4);
                float4 b4 = *reinterpret_cast<const float4*>(bB + k4 * 4);
                float ak[4] = {a4.x, a4.y, a4.z, a4.w};
                float bk[4] = {b4.x, b4.y, b4.z, b4.w};
                #pragma unroll
                for (int kk = 0; kk < 4; kk++) {
                    const int k = k4 * 4 + kk;
                    ulonglong2 w01 = __ldg(wp + k * 112);
                    ulonglong2 w23 = __ldg(wp + k * 112 + 1);
                    const float a = ak[kk], b = bk[kk];
                    unsigned long long aa = pack2(a, a);
                    unsigned long long bb = pack2(b, b);
                    fma2(vA[0], aa, w01.x); fma2(vA[1], aa, w01.y);
                    fma2(vA[2], aa, w23.x); fma2(vA[3], aa, w23.y);
                    fma2(vB[0], bb, w01.x); fma2(vB[1], bb, w01.y);
                    fma2(vB[2], bb, w23.x); fma2(vB[3], bb, w23.y);
                }
            }
            #pragma unroll
            for (int j = 0; j < 4; j++) {
                float lo, hi;
                unpack2(vA[j], lo, hi);
                vsA[2*j] += sp(lo); vsA[2*j+1] += sp(hi);
                unpack2(vB[j], lo, hi);
                vsB[2*j] += sp(lo); vsB[2*j+1] += sp(hi);
            }
        }

        __syncwarp();   // all lanes done reading buf bi before next-iter cp.async reuses it
    }

    // ---- reduce over the 4 fg lanes ----
    #pragma unroll
    for (int c = 0; c < NCOMP; c++) {
        hsA[c] += __shfl_xor_sync(0xffffffffu, hsA[c], 1);
        hsA[c] += __shfl_xor_sync(0xffffffffu, hsA[c], 2);
        vsA[c] += __shfl_xor_sync(0xffffffffu, vsA[c], 1);
        vsA[c] += __shfl_xor_sync(0xffffffffu, vsA[c], 2);
        hsB[c] += __shfl_xor_sync(0xffffffffu, hsB[c], 1);
        hsB[c] += __shfl_xor_sync(0xffffffffu, hsB[c], 2);
        vsB[c] += __shfl_xor_sync(0xffffffffu, vsB[c], 1);
        vsB[c] += __shfl_xor_sync(0xffffffffu, vsB[c], 2);
    }
    icA += __shfl_xor_sync(0xffffffffu, icA, 1);
    icA += __shfl_xor_sync(0xffffffffu, icA, 2);
    icB += __shfl_xor_sync(0xffffffffu, icB, 1);
    icB += __shfl_xor_sync(0xffffffffu, icB, 2);

    if (fg == 0) {
        #pragma unroll
        for (int c = 0; c < NCOMP; c++) {
            float sbh = sp(__ldg(bh + c));
            float sbv = sp(__ldg(bv + c));
            hsA[c] += sbh; hsB[c] += sbh;
            vsA[c] += sbv; vsB[c] += sbv;
        }
        float b0 = __ldg(bic);
        icA += b0; icB += b0;

        // row A = row0 + rp
        {
            float2 o[NCOMP + 1];
            o[0] = make_float2(0.0f, icA);
            float cum = 0.0f, xc = icA;
            #pragma unroll
            for (int c = 0; c < NCOMP; c++) {
                cum += hsA[c];
                xc  += (c & 1) ? -vsA[c] : vsA[c];
                o[c + 1] = make_float2(cum + SEPF * (float)(c + 1), xc);
            }
            o[NCOMP].x = fmaxf(o[NCOMP - 1].x + SEPF, T1F);
            float2* op = reinterpret_cast<float2*>(out + (size_t)(row0 + rp) * 2 * (NCOMP + 1));
            #pragma unroll
            for (int j = 0; j < NCOMP + 1; j++) op[j] = o[j];
        }
        // row B = row0 + rp + 8
        {
            float2 o[NCOMP + 1];
            o[0] = make_float2(0.0f, icB);
            float cum = 0.0f, xc = icB;
            #pragma unroll
            for (int c = 0; c < NCOMP; c++) {
                cum += hsB[c];
                xc  += (c & 1) ? -vsB[c] : vsB[c];
                o[c + 1] = make_float2(cum + SEPF * (float)(c + 1), xc);
            }
            o[NCOMP].x = fmaxf(o[NCOMP - 1].x + SEPF, T1F);
            float2* op = reinterpret_cast<float2*>(out + (size_t)(row0 + rp + 8) * 2 * (NCOMP + 1));
            #pragma unroll
            for (int j = 0; j < NCOMP + 1; j++) op[j] = o[j];
        }
    }
}

extern "C" void kernel_launch(void* const* d_in, const int* in_sizes, int n_in,
                              void* d_out, int out_size)
{
    const float* B    = (const float*)d_in[0];
    const float* Bcat = (const float*)d_in[1];
    const float* Wh   = (const float*)d_in[2];
    const float* Whc  = (const float*)d_in[3];
    const float* bh   = (const float*)d_in[4];
    const float* Wv   = (const float*)d_in[5];
    const float* Wvc  = (const float*)d_in[6];
    const float* bv   = (const float*)d_in[7];
    const float* Wic  = (const float*)d_in[8];
    const float* Wicc = (const float*)d_in[9];
    const float* bic  = (const float*)d_in[10];
    float* out = (float*)d_out;

    const size_t smem = SMEM_F * sizeof(float);   // 43,008 B (< 48 KB)
    k_main<<<BATCH / RPB, TPB, smem>>>(B, Bcat, Wh, bh, Wv, bv, Wic, bic,
                                       Whc, Wvc, Wicc, out);
}